// round 15
// baseline (speedup 1.0000x reference)
#include <cuda_runtime.h>
#include <math.h>

// Problem constants (fixed by the dataset)
#define NN 50000
#define EE 800000
#define HID 64
#define OUTC 8
#define NEG_SLOPE 0.2f
#define SLOT 96          // max edges per destination node (Poisson(16); max~35)
#define FULLM 0xffffffffu

// ---------------- device scratch (no allocations allowed) ----------------
__device__ int g_is64;                        // 1 if edge_index is int64
__device__ __align__(16) int   g_deg[NN];
// fixed-slot bucket store: edge e with dst d lives at g_edge[d*SLOT + k].
// packed record: low32 = src id, high32 = edge_value bits
__device__ __align__(16) unsigned long long g_edge[NN * SLOT];
__device__ __align__(16) float g_h1[NN * HID];
__device__ __align__(16) float g_es1[NN];
__device__ __align__(16) float g_ed1[NN];
__device__ __align__(16) float g_hid[NN * HID];
__device__ __align__(16) float g_h2[NN * OUTC];
__device__ __align__(16) float g_es2[NN];
__device__ __align__(16) float g_ed2[NN];

__device__ __forceinline__ float leaky(float x) {
    return x > 0.f ? x : NEG_SLOPE * x;
}

__device__ __forceinline__ int clampN(int s) {
    return ((unsigned)s < NN) ? s : 0;
}

__device__ __forceinline__ void unpack_edge(unsigned long long rec, int& s, float& v) {
    s = clampN((int)(unsigned)(rec & 0xffffffffull));
    v = __uint_as_float((unsigned)(rec >> 32));
}

// ---- packed f32x2 helpers (FFMA2: ptxas never emits this from C++) ----
__device__ __forceinline__ unsigned long long pack2(float w) {
    unsigned long long r;
    asm("mov.b64 %0, {%1, %1};" : "=l"(r) : "f"(w));
    return r;
}
__device__ __forceinline__ void ffma2(unsigned long long& acc,
                                      unsigned long long a,
                                      unsigned long long w) {
    asm("fma.rn.f32x2 %0, %1, %2, %3;" : "=l"(acc) : "l"(a), "l"(w), "l"(acc));
}
__device__ __forceinline__ unsigned long long add2(unsigned long long a,
                                                   unsigned long long b) {
    unsigned long long r;
    asm("add.rn.f32x2 %0, %1, %2;" : "=l"(r) : "l"(a), "l"(b));
    return r;
}
__device__ __forceinline__ void unpack2(unsigned long long v, float& lo, float& hi) {
    asm("mov.b64 {%0, %1}, %2;" : "=f"(lo), "=f"(hi) : "l"(v));
}
__device__ __forceinline__ unsigned long long d2l(double d) {
    return __double_as_longlong(d);
}

// Fetch an edge-index element honoring the detected dtype (32-bit loads only).
__device__ __forceinline__ int ei_at(const int* ei32, long long idx, int is64) {
    return is64 ? ei32[2 * idx] : ei32[idx];
}

// ---------------- init: zero degrees + dtype detect (merged) ----------------
__global__ void k_init(const int* __restrict__ ei32) {
    int i = blockIdx.x * blockDim.x + threadIdx.x;
    if (i < NN) g_deg[i] = 0;
    if (blockIdx.x == 0) {
        int bad = 0;
        for (int k = threadIdx.x; k < 2048; k += blockDim.x) {
            if (ei32[2 * k + 1] != 0) bad = 1;
        }
        int any = __syncthreads_or(bad);
        if (threadIdx.x == 0) g_is64 = any ? 0 : 1;
    }
}

// ---------------- direct-slot scatter --------
__global__ void k_scatter(const int* __restrict__ ei32,
                          const float* __restrict__ ev) {
    int e = blockIdx.x * blockDim.x + threadIdx.x;
    if (e < EE) {
        int is64 = g_is64;
        int s = ei_at(ei32, e, is64);
        int d = ei_at(ei32, (long long)EE + e, is64);
        if ((unsigned)s < NN && (unsigned)d < NN) {
            int k = atomicAdd(&g_deg[d], 1);
            if (k < SLOT) {
                g_edge[d * SLOT + k] = (unsigned long long)(unsigned)s |
                                       ((unsigned long long)__float_as_uint(ev[e]) << 32);
            }
        }
    }
}

// ---------------- layer 1: h1 = x @ W1 ; e_src/e_dst dots ----------------
__global__ void k_gemm1(const float* __restrict__ x, const float* __restrict__ W1,
                        const float* __restrict__ a1s, const float* __restrict__ a1d) {
    __shared__ float Ws[64 * 64];
    __shared__ float xs[4 * 64];
    __shared__ float ps[8], pd[8];
    int t = threadIdx.x;
    #pragma unroll
    for (int i = t; i < 4096; i += 256) Ws[i] = W1[i];
    int base = blockIdx.x * 4;
    xs[t] = x[base * 64 + t];
    __syncthreads();
    int nl = t >> 6, c = t & 63;
    float sum = 0.f;
    #pragma unroll
    for (int k = 0; k < 64; k++) sum = fmaf(xs[nl * 64 + k], Ws[k * 64 + c], sum);
    int n = base + nl;
    g_h1[n * 64 + c] = sum;
    float vs = sum * a1s[c];
    float vd = sum * a1d[c];
    #pragma unroll
    for (int off = 16; off; off >>= 1) {
        vs += __shfl_xor_sync(FULLM, vs, off);
        vd += __shfl_xor_sync(FULLM, vd, off);
    }
    if ((t & 31) == 0) { ps[t >> 5] = vs; pd[t >> 5] = vd; }
    __syncthreads();
    if (c == 0) {
        g_es1[n] = ps[2 * nl] + ps[2 * nl + 1];
        g_ed1[n] = pd[2 * nl] + pd[2 * nl + 1];
    }
}

// ---------------- layer 1 aggregate: warp per dst node ----------------
__global__ void k_agg1(const float* __restrict__ b1) {
    int w = (blockIdx.x * blockDim.x + threadIdx.x) >> 5;
    if (w >= NN) return;
    int lane = threadIdx.x & 31;
    int deg = g_deg[w];
    deg = max(0, min(deg, SLOT));
    int base = w * SLOT;
    float ed = g_ed1[w];

    if (deg <= 32) {
        // ---- fast path: one edge per lane; softmax via shuffle trees ----
        int   sle = 0;
        float evl = 0.f, l = -INFINITY;
        if (lane < deg) {
            unpack_edge(g_edge[base + lane], sle, evl);
            l = leaky(g_es1[sle] + ed);
        }
        float m = l;
        #pragma unroll
        for (int off = 16; off; off >>= 1) m = fmaxf(m, __shfl_xor_sync(FULLM, m, off));
        float ex = (lane < deg) ? __expf(l - m) : 0.f;
        float den = ex;
        #pragma unroll
        for (int off = 16; off; off >>= 1) den += __shfl_xor_sync(FULLM, den, off);
        float wgt = ex * evl / (den + 1e-16f);

        // ---- gather: half-warp per edge, 4 ch/lane, packed f32x2 FMA ----
        int half = lane >> 4;
        int c4 = (lane & 15) * 4;
        unsigned long long acc01 = 0ull, acc23 = 0ull;   // packed {0,0}

        int j = 0;
        for (; j + 3 < deg; j += 4) {                    // 4 edges / iter, no guards
            int i1 = j + half, i2 = j + 2 + half;        // i1,i2 < deg guaranteed
            float w1 = __shfl_sync(FULLM, wgt, i1);
            int   s1 = __shfl_sync(FULLM, sle, i1);
            float w2 = __shfl_sync(FULLM, wgt, i2);
            int   s2 = __shfl_sync(FULLM, sle, i2);
            double2 hva = *(const double2*)(g_h1 + s1 * 64 + c4);
            double2 hvb = *(const double2*)(g_h1 + s2 * 64 + c4);
            unsigned long long wp1 = pack2(w1), wp2 = pack2(w2);
            ffma2(acc01, d2l(hva.x), wp1);
            ffma2(acc23, d2l(hva.y), wp1);
            ffma2(acc01, d2l(hvb.x), wp2);
            ffma2(acc23, d2l(hvb.y), wp2);
        }
        for (; j < deg; j += 2) {                        // <=2 remainder iters
            int idx = j + half;
            float wj = __shfl_sync(FULLM, wgt, idx & 31);
            int   sj = __shfl_sync(FULLM, sle, idx & 31);
            if (idx < deg) {
                double2 hv = *(const double2*)(g_h1 + sj * 64 + c4);
                unsigned long long wp = pack2(wj);
                ffma2(acc01, d2l(hv.x), wp);
                ffma2(acc23, d2l(hv.y), wp);
            }
        }
        // merge odd-edge half into even-edge half (all lanes execute)
        unsigned long long o01 = __shfl_down_sync(FULLM, acc01, 16);
        unsigned long long o23 = __shfl_down_sync(FULLM, acc23, 16);
        acc01 = add2(acc01, o01);
        acc23 = add2(acc23, o23);
        if (lane < 16) {
            float a0, a1, a2, a3;
            unpack2(acc01, a0, a1);
            unpack2(acc23, a2, a3);
            float4 bv = *(const float4*)(b1 + c4);
            float4 o;
            o.x = fmaxf(a0 + bv.x, 0.f);
            o.y = fmaxf(a1 + bv.y, 0.f);
            o.z = fmaxf(a2 + bv.z, 0.f);
            o.w = fmaxf(a3 + bv.w, 0.f);
            *(float4*)(g_hid + w * 64 + c4) = o;        // fused ReLU, STG.128
        }
    } else {
        // ---- general path (deg in (32,96]; ~0.01% of nodes): 3-pass ----
        int c2 = lane * 2;
        float a0 = 0.f, a1 = 0.f;
        float m = -INFINITY;
        for (int i = lane; i < deg; i += 32) {
            int s; float v; unpack_edge(g_edge[base + i], s, v);
            m = fmaxf(m, leaky(g_es1[s] + ed));
        }
        #pragma unroll
        for (int off = 16; off; off >>= 1) m = fmaxf(m, __shfl_xor_sync(FULLM, m, off));
        float den = 0.f;
        for (int i = lane; i < deg; i += 32) {
            int s; float v; unpack_edge(g_edge[base + i], s, v);
            den += __expf(leaky(g_es1[s] + ed) - m);
        }
        #pragma unroll
        for (int off = 16; off; off >>= 1) den += __shfl_xor_sync(FULLM, den, off);
        float scale = 1.f / (den + 1e-16f);
        int i = 0;
        for (; i + 1 < deg; i += 2) {
            int sa, sb; float va, vb;
            unpack_edge(g_edge[base + i], sa, va);
            unpack_edge(g_edge[base + i + 1], sb, vb);
            float wa = __expf(leaky(g_es1[sa] + ed) - m) * scale * va;
            float wb = __expf(leaky(g_es1[sb] + ed) - m) * scale * vb;
            float2 ha = *(const float2*)(g_h1 + sa * 64 + c2);
            float2 hb = *(const float2*)(g_h1 + sb * 64 + c2);
            a0 = fmaf(wa, ha.x, a0); a1 = fmaf(wa, ha.y, a1);
            a0 = fmaf(wb, hb.x, a0); a1 = fmaf(wb, hb.y, a1);
        }
        if (i < deg) {
            int sa; float va; unpack_edge(g_edge[base + i], sa, va);
            float wa = __expf(leaky(g_es1[sa] + ed) - m) * scale * va;
            float2 ha = *(const float2*)(g_h1 + sa * 64 + c2);
            a0 = fmaf(wa, ha.x, a0); a1 = fmaf(wa, ha.y, a1);
        }
        float o0 = a0 + b1[c2];
        float o1 = a1 + b1[c2 + 1];
        g_hid[w * 64 + c2]     = o0 > 0.f ? o0 : 0.f;
        g_hid[w * 64 + c2 + 1] = o1 > 0.f ? o1 : 0.f;
    }
}

// ---------------- layer 2: h2 = hid @ W2 ; attention dots ----------------
__global__ void k_gemm2(const float* __restrict__ W2,
                        const float* __restrict__ a2s, const float* __restrict__ a2d) {
    __shared__ float Ws[64 * 8];
    __shared__ float hs[32 * 65];
    int t = threadIdx.x;
    for (int i = t; i < 512; i += 256) Ws[i] = W2[i];
    int base = blockIdx.x * 32;
    for (int i = t; i < 2048; i += 256) {
        int nl = i >> 6, k = i & 63;
        int n = base + nl;
        hs[nl * 65 + k] = (n < NN) ? g_hid[n * 64 + k] : 0.f;
    }
    __syncthreads();
    int nl = t >> 3, c = t & 7;
    int n = base + nl;
    float sum = 0.f;
    #pragma unroll
    for (int k = 0; k < 64; k++) sum = fmaf(hs[nl * 65 + k], Ws[k * 8 + c], sum);
    float vs = sum * a2s[c];
    float vd = sum * a2d[c];
    #pragma unroll
    for (int off = 4; off; off >>= 1) {
        vs += __shfl_down_sync(FULLM, vs, off);
        vd += __shfl_down_sync(FULLM, vd, off);
    }
    if (n < NN) {
        g_h2[n * 8 + c] = sum;
        if (c == 0) { g_es2[n] = vs; g_ed2[n] = vd; }
    }
}

// ---------------- layer 2 aggregate + bias + log_softmax ----------------
__global__ void k_agg2(const float* __restrict__ b2, float* __restrict__ out) {
    int w = (blockIdx.x * blockDim.x + threadIdx.x) >> 5;
    if (w >= NN) return;
    int lane = threadIdx.x & 31;
    int deg = g_deg[w];
    deg = max(0, min(deg, SLOT));
    int base = w * SLOT;
    float ed = g_ed2[w];
    int g = lane >> 3, c = lane & 7;
    float acc = 0.f;

    if (deg <= 32) {
        int   sle = 0;
        float evl = 0.f, l = -INFINITY;
        if (lane < deg) {
            unpack_edge(g_edge[base + lane], sle, evl);
            l = leaky(g_es2[sle] + ed);
        }
        float m = l;
        #pragma unroll
        for (int off = 16; off; off >>= 1) m = fmaxf(m, __shfl_xor_sync(FULLM, m, off));
        float ex = (lane < deg) ? __expf(l - m) : 0.f;
        float den = ex;
        #pragma unroll
        for (int off = 16; off; off >>= 1) den += __shfl_xor_sync(FULLM, den, off);
        float wgt = ex * evl / (den + 1e-16f);
        // UNIFORM trip count: all lanes run every shuffle; FMA predicated.
        int nj = (deg + 3) >> 2;
        for (int jj = 0; jj < nj; jj++) {
            int j = jj * 4 + g;
            float wj = __shfl_sync(FULLM, wgt, j & 31);
            int   sj = __shfl_sync(FULLM, sle, j & 31);
            if (j < deg) acc = fmaf(wj, g_h2[sj * 8 + c], acc);
        }
    } else {
        float m = -INFINITY;
        for (int i = lane; i < deg; i += 32) {
            int s; float v; unpack_edge(g_edge[base + i], s, v);
            m = fmaxf(m, leaky(g_es2[s] + ed));
        }
        #pragma unroll
        for (int off = 16; off; off >>= 1) m = fmaxf(m, __shfl_xor_sync(FULLM, m, off));
        float den = 0.f;
        for (int i = lane; i < deg; i += 32) {
            int s; float v; unpack_edge(g_edge[base + i], s, v);
            den += __expf(leaky(g_es2[s] + ed) - m);
        }
        #pragma unroll
        for (int off = 16; off; off >>= 1) den += __shfl_xor_sync(FULLM, den, off);
        float scale = 1.f / (den + 1e-16f);
        for (int i = g; i < deg; i += 4) {
            int s; float v; unpack_edge(g_edge[base + i], s, v);
            float wgt = __expf(leaky(g_es2[s] + ed) - m) * scale * v;
            acc = fmaf(wgt, g_h2[s * 8 + c], acc);
        }
    }
    acc += __shfl_down_sync(FULLM, acc, 16);
    acc += __shfl_down_sync(FULLM, acc, 8);
    float v = acc + b2[c];
    float mx = v;
    #pragma unroll
    for (int off = 1; off < 8; off <<= 1) mx = fmaxf(mx, __shfl_xor_sync(FULLM, mx, off));
    float ex2 = __expf(v - mx);
    float sm = ex2;
    #pragma unroll
    for (int off = 1; off < 8; off <<= 1) sm += __shfl_xor_sync(FULLM, sm, off);
    if (lane < 8) out[w * 8 + c] = v - mx - logf(sm);
}

// ---------------- launch ----------------
extern "C" void kernel_launch(void* const* d_in, const int* in_sizes, int n_in,
                              void* d_out, int out_size) {
    // Identify tensors by size; tolerate in_sizes being ELEMENTS or BYTES.
    int bytes_mode = 0;
    {
        int saw4096 = 0, saw16384 = 0;
        for (int i = 0; i < n_in; i++) {
            if (in_sizes[i] == 4096)  saw4096 = 1;
            if (in_sizes[i] == 16384) saw16384 = 1;
        }
        if (!saw4096 && saw16384) bytes_mode = 1;
    }
    const float* x = 0; const int* ei = 0; const float* ev = 0;
    const float* W1 = 0; const float* W2 = 0;
    const float *a1s = 0, *a1d = 0, *b1 = 0, *a2s = 0, *a2d = 0, *b2 = 0;
    int n64 = 0, n8 = 0;
    for (int i = 0; i < n_in; i++) {
        int s = in_sizes[i];
        const void* p = d_in[i];
        if (!bytes_mode) {
            if      (s == NN * HID)   x  = (const float*)p;
            else if (s == 2 * EE)     ei = (const int*)p;
            else if (s == EE)         ev = (const float*)p;
            else if (s == HID * HID)  W1 = (const float*)p;
            else if (s == HID * OUTC) W2 = (const float*)p;
            else if (s == HID) { if (n64 == 0) a1s = (const float*)p; else if (n64 == 1) a1d = (const float*)p; else b1 = (const float*)p; n64++; }
            else if (s == OUTC) { if (n8 == 0) a2s = (const float*)p; else if (n8 == 1) a2d = (const float*)p; else b2 = (const float*)p; n8++; }
        } else {
            if (s == NN * HID * 4) { if (!x) x = (const float*)p; else if (!ei) ei = (const int*)p; }
            else if (s == 2 * EE * 4) ei = (const int*)p;
            else if (s == EE * 4)     ev = (const float*)p;
            else if (s == HID * HID * 4)  W1 = (const float*)p;
            else if (s == HID * OUTC * 4) W2 = (const float*)p;
            else if (s == HID * 4) { if (n64 == 0) a1s = (const float*)p; else if (n64 == 1) a1d = (const float*)p; else b1 = (const float*)p; n64++; }
            else if (s == OUTC * 4) { if (n8 == 0) a2s = (const float*)p; else if (n8 == 1) a2d = (const float*)p; else b2 = (const float*)p; n8++; }
        }
    }
    if (!x   && n_in > 0)  x   = (const float*)d_in[0];
    if (!ei  && n_in > 1)  ei  = (const int*)d_in[1];
    if (!ev  && n_in > 2)  ev  = (const float*)d_in[2];
    if (!W1  && n_in > 3)  W1  = (const float*)d_in[3];
    if (!a1s && n_in > 4)  a1s = (const float*)d_in[4];
    if (!a1d && n_in > 5)  a1d = (const float*)d_in[5];
    if (!b1  && n_in > 6)  b1  = (const float*)d_in[6];
    if (!W2  && n_in > 7)  W2  = (const float*)d_in[7];
    if (!a2s && n_in > 8)  a2s = (const float*)d_in[8];
    if (!a2d && n_in > 9)  a2d = (const float*)d_in[9];
    if (!b2  && n_in > 10) b2  = (const float*)d_in[10];
    if (!x || !ei || !ev || !W1 || !a1s || !a1d || !b1 || !W2 || !a2s || !a2d || !b2)
        return;
    float* out = (float*)d_out;

    // Fork k_gemm1 (independent of the bucket build) onto a side stream.
    cudaStream_t s2 = 0;
    cudaEvent_t evA = 0, evB = 0;
    bool forked =
        (cudaStreamCreateWithFlags(&s2, cudaStreamNonBlocking) == cudaSuccess) &&
        (cudaEventCreateWithFlags(&evA, cudaEventDisableTiming) == cudaSuccess) &&
        (cudaEventCreateWithFlags(&evB, cudaEventDisableTiming) == cudaSuccess);

    if (forked) {
        cudaEventRecord(evA, 0);
        cudaStreamWaitEvent(s2, evA, 0);
        k_gemm1<<<NN / 4, 256, 0, s2>>>(x, W1, a1s, a1d);
        cudaEventRecord(evB, s2);
    }

    // bucket build on the main stream
    k_init<<<(NN + 255) / 256, 256>>>(ei);
    k_scatter<<<(EE + 255) / 256, 256>>>(ei, ev);

    if (forked) {
        cudaStreamWaitEvent(0, evB, 0);   // join before agg1 consumes h1/es1/ed1
    } else {
        k_gemm1<<<NN / 4, 256>>>(x, W1, a1s, a1d);
    }

    k_agg1<<<(NN * 32 + 255) / 256, 256>>>(b1);
    k_gemm2<<<(NN + 31) / 32, 256>>>(W2, a2s, a2d);
    k_agg2<<<(NN * 32 + 255) / 256, 256>>>(b2, out);
}

// round 16
// speedup vs baseline: 1.0332x; 1.0332x over previous
#include <cuda_runtime.h>
#include <math.h>

// Problem constants (fixed by the dataset)
#define NN 50000
#define EE 800000
#define HID 64
#define OUTC 8
#define NEG_SLOPE 0.2f
#define SLOT 96          // max edges per destination node (Poisson(16); max~35)
#define FULLM 0xffffffffu

// ---------------- device scratch (no allocations allowed) ----------------
__device__ int g_is64;                        // 1 if edge_index is int64
__device__ __align__(16) int   g_deg[NN];
// fixed-slot bucket store: edge e with dst d lives at g_edge[d*SLOT + k].
// packed record: low32 = src id, high32 = edge_value bits
__device__ __align__(16) unsigned long long g_edge[NN * SLOT];
__device__ __align__(16) float g_h1[NN * HID];
__device__ __align__(16) float g_es1[NN];
__device__ __align__(16) float g_ed1[NN];
__device__ __align__(16) float g_hid[NN * HID];
__device__ __align__(16) float g_h2[NN * OUTC];
__device__ __align__(16) float g_es2[NN];
__device__ __align__(16) float g_ed2[NN];

__device__ __forceinline__ float leaky(float x) {
    return x > 0.f ? x : NEG_SLOPE * x;
}

__device__ __forceinline__ int clampN(int s) {
    return ((unsigned)s < NN) ? s : 0;
}

__device__ __forceinline__ void unpack_edge(unsigned long long rec, int& s, float& v) {
    s = clampN((int)(unsigned)(rec & 0xffffffffull));
    v = __uint_as_float((unsigned)(rec >> 32));
}

__device__ __forceinline__ unsigned long long pack_rec(int s, float w) {
    return (unsigned long long)(unsigned)s |
           ((unsigned long long)__float_as_uint(w) << 32);
}
__device__ __forceinline__ void unpack_rec(unsigned long long r, int& s, float& w) {
    s = (int)(unsigned)r;                       // already-clamped src
    w = __uint_as_float((unsigned)(r >> 32));
}

// Fetch an edge-index element honoring the detected dtype (32-bit loads only).
__device__ __forceinline__ int ei_at(const int* ei32, long long idx, int is64) {
    return is64 ? ei32[2 * idx] : ei32[idx];
}

// ---------------- init: zero degrees + dtype detect (merged) ----------------
__global__ void k_init(const int* __restrict__ ei32) {
    int i = blockIdx.x * blockDim.x + threadIdx.x;
    if (i < NN) g_deg[i] = 0;
    if (blockIdx.x == 0) {
        int bad = 0;
        for (int k = threadIdx.x; k < 2048; k += blockDim.x) {
            if (ei32[2 * k + 1] != 0) bad = 1;
        }
        int any = __syncthreads_or(bad);
        if (threadIdx.x == 0) g_is64 = any ? 0 : 1;
    }
}

// ---------------- direct-slot scatter --------
__global__ void k_scatter(const int* __restrict__ ei32,
                          const float* __restrict__ ev) {
    int e = blockIdx.x * blockDim.x + threadIdx.x;
    if (e < EE) {
        int is64 = g_is64;
        int s = ei_at(ei32, e, is64);
        int d = ei_at(ei32, (long long)EE + e, is64);
        if ((unsigned)s < NN && (unsigned)d < NN) {
            int k = atomicAdd(&g_deg[d], 1);
            if (k < SLOT) {
                g_edge[d * SLOT + k] = (unsigned long long)(unsigned)s |
                                       ((unsigned long long)__float_as_uint(ev[e]) << 32);
            }
        }
    }
}

// ---------------- layer 1: h1 = x @ W1 ; e_src/e_dst dots ----------------
__global__ void k_gemm1(const float* __restrict__ x, const float* __restrict__ W1,
                        const float* __restrict__ a1s, const float* __restrict__ a1d) {
    __shared__ float Ws[64 * 64];
    __shared__ float xs[4 * 64];
    __shared__ float ps[8], pd[8];
    int t = threadIdx.x;
    #pragma unroll
    for (int i = t; i < 4096; i += 256) Ws[i] = W1[i];
    int base = blockIdx.x * 4;
    xs[t] = x[base * 64 + t];
    __syncthreads();
    int nl = t >> 6, c = t & 63;
    float sum = 0.f;
    #pragma unroll
    for (int k = 0; k < 64; k++) sum = fmaf(xs[nl * 64 + k], Ws[k * 64 + c], sum);
    int n = base + nl;
    g_h1[n * 64 + c] = sum;
    float vs = sum * a1s[c];
    float vd = sum * a1d[c];
    #pragma unroll
    for (int off = 16; off; off >>= 1) {
        vs += __shfl_xor_sync(FULLM, vs, off);
        vd += __shfl_xor_sync(FULLM, vd, off);
    }
    if ((t & 31) == 0) { ps[t >> 5] = vs; pd[t >> 5] = vd; }
    __syncthreads();
    if (c == 0) {
        g_es1[n] = ps[2 * nl] + ps[2 * nl + 1];
        g_ed1[n] = pd[2 * nl] + pd[2 * nl + 1];
    }
}

// ---------------- layer 1 aggregate: warp per dst node ----------------
// R14 structure (2 ch/lane, whole-warp per edge) with shuffle-broadcast
// replaced by shared-memory record broadcast (LDS.128 = 4 edges' metadata).
__global__ void k_agg1(const float* __restrict__ b1) {
    __shared__ __align__(16) unsigned long long swrec[8][34];  // 8 warps/block
    int w = (blockIdx.x * blockDim.x + threadIdx.x) >> 5;
    if (w >= NN) return;
    int lane = threadIdx.x & 31;
    int wblk = (threadIdx.x >> 5) & 7;
    int deg = g_deg[w];
    deg = max(0, min(deg, SLOT));
    int base = w * SLOT;
    float ed = g_ed1[w];
    int c2 = lane * 2;
    float a0 = 0.f, a1 = 0.f;

    if (deg <= 32) {
        // fast path: one edge per lane; softmax via shuffle trees
        int   sle = 0;
        float evl = 0.f, l = -INFINITY;
        if (lane < deg) {
            unpack_edge(g_edge[base + lane], sle, evl);
            l = leaky(g_es1[sle] + ed);
        }
        float m = l;
        #pragma unroll
        for (int off = 16; off; off >>= 1) m = fmaxf(m, __shfl_xor_sync(FULLM, m, off));
        float ex = (lane < deg) ? __expf(l - m) : 0.f;
        float den = ex;
        #pragma unroll
        for (int off = 16; off; off >>= 1) den += __shfl_xor_sync(FULLM, den, off);
        float wgt = ex * evl / (den + 1e-16f);

        // publish (src, wgt) records once; loop reads them via LDS broadcast
        swrec[wblk][lane] = pack_rec(sle, wgt);
        __syncwarp();
        const unsigned long long* rec = swrec[wblk];

        int j = 0;
        for (; j + 3 < deg; j += 4) {
            ulonglong2 rA = *(const ulonglong2*)(rec + j);      // edges j, j+1
            ulonglong2 rB = *(const ulonglong2*)(rec + j + 2);  // edges j+2, j+3
            int s0, s1, s2, s3; float w0, w1, w2, w3;
            unpack_rec(rA.x, s0, w0);
            unpack_rec(rA.y, s1, w1);
            unpack_rec(rB.x, s2, w2);
            unpack_rec(rB.y, s3, w3);
            float2 ha = *(const float2*)(g_h1 + s0 * 64 + c2);
            float2 hb = *(const float2*)(g_h1 + s1 * 64 + c2);
            float2 hc = *(const float2*)(g_h1 + s2 * 64 + c2);
            float2 hd = *(const float2*)(g_h1 + s3 * 64 + c2);
            a0 = fmaf(w0, ha.x, a0); a1 = fmaf(w0, ha.y, a1);
            a0 = fmaf(w1, hb.x, a0); a1 = fmaf(w1, hb.y, a1);
            a0 = fmaf(w2, hc.x, a0); a1 = fmaf(w2, hc.y, a1);
            a0 = fmaf(w3, hd.x, a0); a1 = fmaf(w3, hd.y, a1);
        }
        for (; j < deg; j++) {
            int s0; float w0;
            unpack_rec(rec[j], s0, w0);
            float2 ha = *(const float2*)(g_h1 + s0 * 64 + c2);
            a0 = fmaf(w0, ha.x, a0); a1 = fmaf(w0, ha.y, a1);
        }
    } else {
        // general path (deg in (32,96]; rare): 3-pass
        float m = -INFINITY;
        for (int i = lane; i < deg; i += 32) {
            int s; float v; unpack_edge(g_edge[base + i], s, v);
            m = fmaxf(m, leaky(g_es1[s] + ed));
        }
        #pragma unroll
        for (int off = 16; off; off >>= 1) m = fmaxf(m, __shfl_xor_sync(FULLM, m, off));
        float den = 0.f;
        for (int i = lane; i < deg; i += 32) {
            int s; float v; unpack_edge(g_edge[base + i], s, v);
            den += __expf(leaky(g_es1[s] + ed) - m);
        }
        #pragma unroll
        for (int off = 16; off; off >>= 1) den += __shfl_xor_sync(FULLM, den, off);
        float scale = 1.f / (den + 1e-16f);
        int i = 0;
        for (; i + 1 < deg; i += 2) {
            int sa, sb; float va, vb;
            unpack_edge(g_edge[base + i], sa, va);
            unpack_edge(g_edge[base + i + 1], sb, vb);
            float wa = __expf(leaky(g_es1[sa] + ed) - m) * scale * va;
            float wb = __expf(leaky(g_es1[sb] + ed) - m) * scale * vb;
            float2 ha = *(const float2*)(g_h1 + sa * 64 + c2);
            float2 hb = *(const float2*)(g_h1 + sb * 64 + c2);
            a0 = fmaf(wa, ha.x, a0); a1 = fmaf(wa, ha.y, a1);
            a0 = fmaf(wb, hb.x, a0); a1 = fmaf(wb, hb.y, a1);
        }
        if (i < deg) {
            int sa; float va; unpack_edge(g_edge[base + i], sa, va);
            float wa = __expf(leaky(g_es1[sa] + ed) - m) * scale * va;
            float2 ha = *(const float2*)(g_h1 + sa * 64 + c2);
            a0 = fmaf(wa, ha.x, a0); a1 = fmaf(wa, ha.y, a1);
        }
    }
    float o0 = a0 + b1[c2];
    float o1 = a1 + b1[c2 + 1];
    g_hid[w * 64 + c2]     = o0 > 0.f ? o0 : 0.f;   // fused ReLU
    g_hid[w * 64 + c2 + 1] = o1 > 0.f ? o1 : 0.f;
}

// ---------------- layer 2: h2 = hid @ W2 ; attention dots ----------------
__global__ void k_gemm2(const float* __restrict__ W2,
                        const float* __restrict__ a2s, const float* __restrict__ a2d) {
    __shared__ float Ws[64 * 8];
    __shared__ float hs[32 * 65];
    int t = threadIdx.x;
    for (int i = t; i < 512; i += 256) Ws[i] = W2[i];
    int base = blockIdx.x * 32;
    for (int i = t; i < 2048; i += 256) {
        int nl = i >> 6, k = i & 63;
        int n = base + nl;
        hs[nl * 65 + k] = (n < NN) ? g_hid[n * 64 + k] : 0.f;
    }
    __syncthreads();
    int nl = t >> 3, c = t & 7;
    int n = base + nl;
    float sum = 0.f;
    #pragma unroll
    for (int k = 0; k < 64; k++) sum = fmaf(hs[nl * 65 + k], Ws[k * 8 + c], sum);
    float vs = sum * a2s[c];
    float vd = sum * a2d[c];
    #pragma unroll
    for (int off = 4; off; off >>= 1) {
        vs += __shfl_down_sync(FULLM, vs, off);
        vd += __shfl_down_sync(FULLM, vd, off);
    }
    if (n < NN) {
        g_h2[n * 8 + c] = sum;
        if (c == 0) { g_es2[n] = vs; g_ed2[n] = vd; }
    }
}

// ---------------- layer 2 aggregate + bias + log_softmax ----------------
__global__ void k_agg2(const float* __restrict__ b2, float* __restrict__ out) {
    __shared__ __align__(16) unsigned long long swrec[8][34];
    int w = (blockIdx.x * blockDim.x + threadIdx.x) >> 5;
    if (w >= NN) return;
    int lane = threadIdx.x & 31;
    int wblk = (threadIdx.x >> 5) & 7;
    int deg = g_deg[w];
    deg = max(0, min(deg, SLOT));
    int base = w * SLOT;
    float ed = g_ed2[w];
    int g = lane >> 3, c = lane & 7;
    float acc = 0.f;

    if (deg <= 32) {
        int   sle = 0;
        float evl = 0.f, l = -INFINITY;
        if (lane < deg) {
            unpack_edge(g_edge[base + lane], sle, evl);
            l = leaky(g_es2[sle] + ed);
        }
        float m = l;
        #pragma unroll
        for (int off = 16; off; off >>= 1) m = fmaxf(m, __shfl_xor_sync(FULLM, m, off));
        float ex = (lane < deg) ? __expf(l - m) : 0.f;
        float den = ex;
        #pragma unroll
        for (int off = 16; off; off >>= 1) den += __shfl_xor_sync(FULLM, den, off);
        float wgt = ex * evl / (den + 1e-16f);

        swrec[wblk][lane] = pack_rec(sle, wgt);
        __syncwarp();
        // UNIFORM trip count; LDS record read replaces two shuffles.
        int nj = (deg + 3) >> 2;
        for (int jj = 0; jj < nj; jj++) {
            int j = jj * 4 + g;
            int sj; float wj;
            unpack_rec(swrec[wblk][j & 31], sj, wj);
            if (j < deg) acc = fmaf(wj, g_h2[sj * 8 + c], acc);
        }
    } else {
        float m = -INFINITY;
        for (int i = lane; i < deg; i += 32) {
            int s; float v; unpack_edge(g_edge[base + i], s, v);
            m = fmaxf(m, leaky(g_es2[s] + ed));
        }
        #pragma unroll
        for (int off = 16; off; off >>= 1) m = fmaxf(m, __shfl_xor_sync(FULLM, m, off));
        float den = 0.f;
        for (int i = lane; i < deg; i += 32) {
            int s; float v; unpack_edge(g_edge[base + i], s, v);
            den += __expf(leaky(g_es2[s] + ed) - m);
        }
        #pragma unroll
        for (int off = 16; off; off >>= 1) den += __shfl_xor_sync(FULLM, den, off);
        float scale = 1.f / (den + 1e-16f);
        for (int i = g; i < deg; i += 4) {
            int s; float v; unpack_edge(g_edge[base + i], s, v);
            float wgt = __expf(leaky(g_es2[s] + ed) - m) * scale * v;
            acc = fmaf(wgt, g_h2[s * 8 + c], acc);
        }
    }
    acc += __shfl_down_sync(FULLM, acc, 16);
    acc += __shfl_down_sync(FULLM, acc, 8);
    float v = acc + b2[c];
    float mx = v;
    #pragma unroll
    for (int off = 1; off < 8; off <<= 1) mx = fmaxf(mx, __shfl_xor_sync(FULLM, mx, off));
    float ex2 = __expf(v - mx);
    float sm = ex2;
    #pragma unroll
    for (int off = 1; off < 8; off <<= 1) sm += __shfl_xor_sync(FULLM, sm, off);
    if (lane < 8) out[w * 8 + c] = v - mx - logf(sm);
}

// ---------------- launch ----------------
extern "C" void kernel_launch(void* const* d_in, const int* in_sizes, int n_in,
                              void* d_out, int out_size) {
    // Identify tensors by size; tolerate in_sizes being ELEMENTS or BYTES.
    int bytes_mode = 0;
    {
        int saw4096 = 0, saw16384 = 0;
        for (int i = 0; i < n_in; i++) {
            if (in_sizes[i] == 4096)  saw4096 = 1;
            if (in_sizes[i] == 16384) saw16384 = 1;
        }
        if (!saw4096 && saw16384) bytes_mode = 1;
    }
    const float* x = 0; const int* ei = 0; const float* ev = 0;
    const float* W1 = 0; const float* W2 = 0;
    const float *a1s = 0, *a1d = 0, *b1 = 0, *a2s = 0, *a2d = 0, *b2 = 0;
    int n64 = 0, n8 = 0;
    for (int i = 0; i < n_in; i++) {
        int s = in_sizes[i];
        const void* p = d_in[i];
        if (!bytes_mode) {
            if      (s == NN * HID)   x  = (const float*)p;
            else if (s == 2 * EE)     ei = (const int*)p;
            else if (s == EE)         ev = (const float*)p;
            else if (s == HID * HID)  W1 = (const float*)p;
            else if (s == HID * OUTC) W2 = (const float*)p;
            else if (s == HID) { if (n64 == 0) a1s = (const float*)p; else if (n64 == 1) a1d = (const float*)p; else b1 = (const float*)p; n64++; }
            else if (s == OUTC) { if (n8 == 0) a2s = (const float*)p; else if (n8 == 1) a2d = (const float*)p; else b2 = (const float*)p; n8++; }
        } else {
            if (s == NN * HID * 4) { if (!x) x = (const float*)p; else if (!ei) ei = (const int*)p; }
            else if (s == 2 * EE * 4) ei = (const int*)p;
            else if (s == EE * 4)     ev = (const float*)p;
            else if (s == HID * HID * 4)  W1 = (const float*)p;
            else if (s == HID * OUTC * 4) W2 = (const float*)p;
            else if (s == HID * 4) { if (n64 == 0) a1s = (const float*)p; else if (n64 == 1) a1d = (const float*)p; else b1 = (const float*)p; n64++; }
            else if (s == OUTC * 4) { if (n8 == 0) a2s = (const float*)p; else if (n8 == 1) a2d = (const float*)p; else b2 = (const float*)p; n8++; }
        }
    }
    if (!x   && n_in > 0)  x   = (const float*)d_in[0];
    if (!ei  && n_in > 1)  ei  = (const int*)d_in[1];
    if (!ev  && n_in > 2)  ev  = (const float*)d_in[2];
    if (!W1  && n_in > 3)  W1  = (const float*)d_in[3];
    if (!a1s && n_in > 4)  a1s = (const float*)d_in[4];
    if (!a1d && n_in > 5)  a1d = (const float*)d_in[5];
    if (!b1  && n_in > 6)  b1  = (const float*)d_in[6];
    if (!W2  && n_in > 7)  W2  = (const float*)d_in[7];
    if (!a2s && n_in > 8)  a2s = (const float*)d_in[8];
    if (!a2d && n_in > 9)  a2d = (const float*)d_in[9];
    if (!b2  && n_in > 10) b2  = (const float*)d_in[10];
    if (!x || !ei || !ev || !W1 || !a1s || !a1d || !b1 || !W2 || !a2s || !a2d || !b2)
        return;
    float* out = (float*)d_out;

    // Fork k_gemm1 (independent of the bucket build) onto a side stream.
    cudaStream_t s2 = 0;
    cudaEvent_t evA = 0, evB = 0;
    bool forked =
        (cudaStreamCreateWithFlags(&s2, cudaStreamNonBlocking) == cudaSuccess) &&
        (cudaEventCreateWithFlags(&evA, cudaEventDisableTiming) == cudaSuccess) &&
        (cudaEventCreateWithFlags(&evB, cudaEventDisableTiming) == cudaSuccess);

    if (forked) {
        cudaEventRecord(evA, 0);
        cudaStreamWaitEvent(s2, evA, 0);
        k_gemm1<<<NN / 4, 256, 0, s2>>>(x, W1, a1s, a1d);
        cudaEventRecord(evB, s2);
    }

    // bucket build on the main stream
    k_init<<<(NN + 255) / 256, 256>>>(ei);
    k_scatter<<<(EE + 255) / 256, 256>>>(ei, ev);

    if (forked) {
        cudaStreamWaitEvent(0, evB, 0);   // join before agg1 consumes h1/es1/ed1
    } else {
        k_gemm1<<<NN / 4, 256>>>(x, W1, a1s, a1d);
    }

    k_agg1<<<(NN * 32 + 255) / 256, 256>>>(b1);
    k_gemm2<<<(NN + 31) / 32, 256>>>(W2, a2s, a2d);
    k_agg2<<<(NN * 32 + 255) / 256, 256>>>(b2, out);
}

// round 17
// speedup vs baseline: 1.0608x; 1.0267x over previous
#include <cuda_runtime.h>
#include <math.h>

// Problem constants (fixed by the dataset)
#define NN 50000
#define EE 800000
#define HID 64
#define OUTC 8
#define NEG_SLOPE 0.2f
#define SLOT 96          // max edges per destination node (Poisson(16); max~35)
#define FULLM 0xffffffffu

// ---------------- device scratch (no allocations allowed) ----------------
__device__ int g_is64;                        // 1 if edge_index is int64
__device__ __align__(16) int   g_deg[NN];
// fixed-slot bucket store: edge e with dst d lives at g_edge[d*SLOT + k].
// packed record: low32 = src id, high32 = edge_value bits
__device__ __align__(16) unsigned long long g_edge[NN * SLOT];
__device__ __align__(16) float g_h1[NN * HID];
__device__ __align__(16) float g_es1[NN];
__device__ __align__(16) float g_ed1[NN];
__device__ __align__(16) float g_hid[NN * HID];
__device__ __align__(16) float g_h2[NN * OUTC];
__device__ __align__(16) float g_es2[NN];
__device__ __align__(16) float g_ed2[NN];

__device__ __forceinline__ float leaky(float x) {
    return x > 0.f ? x : NEG_SLOPE * x;
}

__device__ __forceinline__ int clampN(int s) {
    return ((unsigned)s < NN) ? s : 0;
}

__device__ __forceinline__ void unpack_edge(unsigned long long rec, int& s, float& v) {
    s = clampN((int)(unsigned)(rec & 0xffffffffull));
    v = __uint_as_float((unsigned)(rec >> 32));
}

__device__ __forceinline__ unsigned long long pack_rec(int s, float w) {
    return (unsigned long long)(unsigned)s |
           ((unsigned long long)__float_as_uint(w) << 32);
}
__device__ __forceinline__ void unpack_rec(unsigned long long r, int& s, float& w) {
    s = (int)(unsigned)r;                       // already-clamped src
    w = __uint_as_float((unsigned)(r >> 32));
}

__device__ __forceinline__ unsigned long long mk_rec(int s, float v) {
    return (unsigned long long)(unsigned)s |
           ((unsigned long long)__float_as_uint(v) << 32);
}

// ---------------- init: zero degrees + dtype detect (merged) ----------------
__global__ void k_init(const int* __restrict__ ei32) {
    int i = blockIdx.x * blockDim.x + threadIdx.x;
    if (i < NN) g_deg[i] = 0;
    if (blockIdx.x == 0) {
        int bad = 0;
        for (int k = threadIdx.x; k < 2048; k += blockDim.x) {
            if (ei32[2 * k + 1] != 0) bad = 1;
        }
        int any = __syncthreads_or(bad);
        if (threadIdx.x == 0) g_is64 = any ? 0 : 1;
    }
}

// ---------------- direct-slot scatter: 2 edges per thread, vector loads ----
__global__ void k_scatter(const int* __restrict__ ei32,
                          const float* __restrict__ ev) {
    int t = blockIdx.x * blockDim.x + threadIdx.x;
    if (t >= EE / 2) return;
    int s0, s1, d0, d1;
    if (g_is64) {
        // int64 indices: int4 = two little-endian int64 values (low words .x/.z)
        int4 sp = ((const int4*)ei32)[t];
        int4 dp = ((const int4*)ei32)[(EE / 2) + t];   // dst section starts at word 2*EE
        s0 = sp.x; s1 = sp.z;
        d0 = dp.x; d1 = dp.z;
    } else {
        int2 sp = ((const int2*)ei32)[t];
        int2 dp = ((const int2*)ei32)[(EE / 2) + t];
        s0 = sp.x; s1 = sp.y;
        d0 = dp.x; d1 = dp.y;
    }
    float2 vv = ((const float2*)ev)[t];
    if ((unsigned)s0 < NN && (unsigned)d0 < NN) {
        int k = atomicAdd(&g_deg[d0], 1);
        if (k < SLOT) g_edge[d0 * SLOT + k] = mk_rec(s0, vv.x);
    }
    if ((unsigned)s1 < NN && (unsigned)d1 < NN) {
        int k = atomicAdd(&g_deg[d1], 1);
        if (k < SLOT) g_edge[d1 * SLOT + k] = mk_rec(s1, vv.y);
    }
}

// ---------------- layer 1: h1 = x @ W1 ; e_src/e_dst dots ----------------
__global__ void k_gemm1(const float* __restrict__ x, const float* __restrict__ W1,
                        const float* __restrict__ a1s, const float* __restrict__ a1d) {
    __shared__ float Ws[64 * 64];
    __shared__ float xs[4 * 64];
    __shared__ float ps[8], pd[8];
    int t = threadIdx.x;
    #pragma unroll
    for (int i = t; i < 4096; i += 256) Ws[i] = W1[i];
    int base = blockIdx.x * 4;
    xs[t] = x[base * 64 + t];
    __syncthreads();
    int nl = t >> 6, c = t & 63;
    float sum = 0.f;
    #pragma unroll
    for (int k = 0; k < 64; k++) sum = fmaf(xs[nl * 64 + k], Ws[k * 64 + c], sum);
    int n = base + nl;
    g_h1[n * 64 + c] = sum;
    float vs = sum * a1s[c];
    float vd = sum * a1d[c];
    #pragma unroll
    for (int off = 16; off; off >>= 1) {
        vs += __shfl_xor_sync(FULLM, vs, off);
        vd += __shfl_xor_sync(FULLM, vd, off);
    }
    if ((t & 31) == 0) { ps[t >> 5] = vs; pd[t >> 5] = vd; }
    __syncthreads();
    if (c == 0) {
        g_es1[n] = ps[2 * nl] + ps[2 * nl + 1];
        g_ed1[n] = pd[2 * nl] + pd[2 * nl + 1];
    }
}

// ---------------- layer 1 aggregate: warp per dst node ----------------
__global__ void k_agg1(const float* __restrict__ b1) {
    __shared__ __align__(16) unsigned long long swrec[8][34];  // 8 warps/block
    int w = (blockIdx.x * blockDim.x + threadIdx.x) >> 5;
    if (w >= NN) return;
    int lane = threadIdx.x & 31;
    int wblk = (threadIdx.x >> 5) & 7;
    int deg = g_deg[w];
    deg = max(0, min(deg, SLOT));
    int base = w * SLOT;
    float ed = g_ed1[w];
    int c2 = lane * 2;
    float a0 = 0.f, a1 = 0.f;

    if (deg <= 32) {
        // fast path: one edge per lane; softmax via shuffle trees
        int   sle = 0;
        float evl = 0.f, l = -INFINITY;
        if (lane < deg) {
            unpack_edge(g_edge[base + lane], sle, evl);
            l = leaky(g_es1[sle] + ed);
        }
        float m = l;
        #pragma unroll
        for (int off = 16; off; off >>= 1) m = fmaxf(m, __shfl_xor_sync(FULLM, m, off));
        float ex = (lane < deg) ? __expf(l - m) : 0.f;
        float den = ex;
        #pragma unroll
        for (int off = 16; off; off >>= 1) den += __shfl_xor_sync(FULLM, den, off);
        float wgt = ex * evl * __fdividef(1.f, den + 1e-16f);   // fast rcp

        // publish (src, wgt) records once; loop reads them via LDS broadcast
        swrec[wblk][lane] = pack_rec(sle, wgt);
        __syncwarp();
        const unsigned long long* rec = swrec[wblk];

        int j = 0;
        for (; j + 3 < deg; j += 4) {
            ulonglong2 rA = *(const ulonglong2*)(rec + j);      // edges j, j+1
            ulonglong2 rB = *(const ulonglong2*)(rec + j + 2);  // edges j+2, j+3
            int s0, s1, s2, s3; float w0, w1, w2, w3;
            unpack_rec(rA.x, s0, w0);
            unpack_rec(rA.y, s1, w1);
            unpack_rec(rB.x, s2, w2);
            unpack_rec(rB.y, s3, w3);
            float2 ha = *(const float2*)(g_h1 + s0 * 64 + c2);
            float2 hb = *(const float2*)(g_h1 + s1 * 64 + c2);
            float2 hc = *(const float2*)(g_h1 + s2 * 64 + c2);
            float2 hd = *(const float2*)(g_h1 + s3 * 64 + c2);
            a0 = fmaf(w0, ha.x, a0); a1 = fmaf(w0, ha.y, a1);
            a0 = fmaf(w1, hb.x, a0); a1 = fmaf(w1, hb.y, a1);
            a0 = fmaf(w2, hc.x, a0); a1 = fmaf(w2, hc.y, a1);
            a0 = fmaf(w3, hd.x, a0); a1 = fmaf(w3, hd.y, a1);
        }
        for (; j < deg; j++) {
            int s0; float w0;
            unpack_rec(rec[j], s0, w0);
            float2 ha = *(const float2*)(g_h1 + s0 * 64 + c2);
            a0 = fmaf(w0, ha.x, a0); a1 = fmaf(w0, ha.y, a1);
        }
    } else {
        // general path (deg in (32,96]; rare): 3-pass
        float m = -INFINITY;
        for (int i = lane; i < deg; i += 32) {
            int s; float v; unpack_edge(g_edge[base + i], s, v);
            m = fmaxf(m, leaky(g_es1[s] + ed));
        }
        #pragma unroll
        for (int off = 16; off; off >>= 1) m = fmaxf(m, __shfl_xor_sync(FULLM, m, off));
        float den = 0.f;
        for (int i = lane; i < deg; i += 32) {
            int s; float v; unpack_edge(g_edge[base + i], s, v);
            den += __expf(leaky(g_es1[s] + ed) - m);
        }
        #pragma unroll
        for (int off = 16; off; off >>= 1) den += __shfl_xor_sync(FULLM, den, off);
        float scale = __fdividef(1.f, den + 1e-16f);
        int i = 0;
        for (; i + 1 < deg; i += 2) {
            int sa, sb; float va, vb;
            unpack_edge(g_edge[base + i], sa, va);
            unpack_edge(g_edge[base + i + 1], sb, vb);
            float wa = __expf(leaky(g_es1[sa] + ed) - m) * scale * va;
            float wb = __expf(leaky(g_es1[sb] + ed) - m) * scale * vb;
            float2 ha = *(const float2*)(g_h1 + sa * 64 + c2);
            float2 hb = *(const float2*)(g_h1 + sb * 64 + c2);
            a0 = fmaf(wa, ha.x, a0); a1 = fmaf(wa, ha.y, a1);
            a0 = fmaf(wb, hb.x, a0); a1 = fmaf(wb, hb.y, a1);
        }
        if (i < deg) {
            int sa; float va; unpack_edge(g_edge[base + i], sa, va);
            float wa = __expf(leaky(g_es1[sa] + ed) - m) * scale * va;
            float2 ha = *(const float2*)(g_h1 + sa * 64 + c2);
            a0 = fmaf(wa, ha.x, a0); a1 = fmaf(wa, ha.y, a1);
        }
    }
    float o0 = a0 + b1[c2];
    float o1 = a1 + b1[c2 + 1];
    g_hid[w * 64 + c2]     = o0 > 0.f ? o0 : 0.f;   // fused ReLU
    g_hid[w * 64 + c2 + 1] = o1 > 0.f ? o1 : 0.f;
}

// ---------------- layer 2: h2 = hid @ W2 ; attention dots ----------------
__global__ void k_gemm2(const float* __restrict__ W2,
                        const float* __restrict__ a2s, const float* __restrict__ a2d) {
    __shared__ float Ws[64 * 8];
    __shared__ float hs[32 * 65];
    int t = threadIdx.x;
    for (int i = t; i < 512; i += 256) Ws[i] = W2[i];
    int base = blockIdx.x * 32;
    for (int i = t; i < 2048; i += 256) {
        int nl = i >> 6, k = i & 63;
        int n = base + nl;
        hs[nl * 65 + k] = (n < NN) ? g_hid[n * 64 + k] : 0.f;
    }
    __syncthreads();
    int nl = t >> 3, c = t & 7;
    int n = base + nl;
    float sum = 0.f;
    #pragma unroll
    for (int k = 0; k < 64; k++) sum = fmaf(hs[nl * 65 + k], Ws[k * 8 + c], sum);
    float vs = sum * a2s[c];
    float vd = sum * a2d[c];
    #pragma unroll
    for (int off = 4; off; off >>= 1) {
        vs += __shfl_down_sync(FULLM, vs, off);
        vd += __shfl_down_sync(FULLM, vd, off);
    }
    if (n < NN) {
        g_h2[n * 8 + c] = sum;
        if (c == 0) { g_es2[n] = vs; g_ed2[n] = vd; }
    }
}

// ---------------- layer 2 aggregate + bias + log_softmax ----------------
__global__ void k_agg2(const float* __restrict__ b2, float* __restrict__ out) {
    __shared__ __align__(16) unsigned long long swrec[8][34];
    int w = (blockIdx.x * blockDim.x + threadIdx.x) >> 5;
    if (w >= NN) return;
    int lane = threadIdx.x & 31;
    int wblk = (threadIdx.x >> 5) & 7;
    int deg = g_deg[w];
    deg = max(0, min(deg, SLOT));
    int base = w * SLOT;
    float ed = g_ed2[w];
    int g = lane >> 3, c = lane & 7;
    float acc = 0.f;

    if (deg <= 32) {
        int   sle = 0;
        float evl = 0.f, l = -INFINITY;
        if (lane < deg) {
            unpack_edge(g_edge[base + lane], sle, evl);
            l = leaky(g_es2[sle] + ed);
        }
        float m = l;
        #pragma unroll
        for (int off = 16; off; off >>= 1) m = fmaxf(m, __shfl_xor_sync(FULLM, m, off));
        float ex = (lane < deg) ? __expf(l - m) : 0.f;
        float den = ex;
        #pragma unroll
        for (int off = 16; off; off >>= 1) den += __shfl_xor_sync(FULLM, den, off);
        float wgt = ex * evl * __fdividef(1.f, den + 1e-16f);

        swrec[wblk][lane] = pack_rec(sle, wgt);
        __syncwarp();
        // UNIFORM trip count; LDS record read replaces two shuffles.
        int nj = (deg + 3) >> 2;
        for (int jj = 0; jj < nj; jj++) {
            int j = jj * 4 + g;
            int sj; float wj;
            unpack_rec(swrec[wblk][j & 31], sj, wj);
            if (j < deg) acc = fmaf(wj, g_h2[sj * 8 + c], acc);
        }
    } else {
        float m = -INFINITY;
        for (int i = lane; i < deg; i += 32) {
            int s; float v; unpack_edge(g_edge[base + i], s, v);
            m = fmaxf(m, leaky(g_es2[s] + ed));
        }
        #pragma unroll
        for (int off = 16; off; off >>= 1) m = fmaxf(m, __shfl_xor_sync(FULLM, m, off));
        float den = 0.f;
        for (int i = lane; i < deg; i += 32) {
            int s; float v; unpack_edge(g_edge[base + i], s, v);
            den += __expf(leaky(g_es2[s] + ed) - m);
        }
        #pragma unroll
        for (int off = 16; off; off >>= 1) den += __shfl_xor_sync(FULLM, den, off);
        float scale = __fdividef(1.f, den + 1e-16f);
        for (int i = g; i < deg; i += 4) {
            int s; float v; unpack_edge(g_edge[base + i], s, v);
            float wgt = __expf(leaky(g_es2[s] + ed) - m) * scale * v;
            acc = fmaf(wgt, g_h2[s * 8 + c], acc);
        }
    }
    acc += __shfl_down_sync(FULLM, acc, 16);
    acc += __shfl_down_sync(FULLM, acc, 8);
    float v = acc + b2[c];
    float mx = v;
    #pragma unroll
    for (int off = 1; off < 8; off <<= 1) mx = fmaxf(mx, __shfl_xor_sync(FULLM, mx, off));
    float ex2 = __expf(v - mx);
    float sm = ex2;
    #pragma unroll
    for (int off = 1; off < 8; off <<= 1) sm += __shfl_xor_sync(FULLM, sm, off);
    if (lane < 8) out[w * 8 + c] = v - mx - logf(sm);
}

// ---------------- launch ----------------
extern "C" void kernel_launch(void* const* d_in, const int* in_sizes, int n_in,
                              void* d_out, int out_size) {
    // Identify tensors by size; tolerate in_sizes being ELEMENTS or BYTES.
    int bytes_mode = 0;
    {
        int saw4096 = 0, saw16384 = 0;
        for (int i = 0; i < n_in; i++) {
            if (in_sizes[i] == 4096)  saw4096 = 1;
            if (in_sizes[i] == 16384) saw16384 = 1;
        }
        if (!saw4096 && saw16384) bytes_mode = 1;
    }
    const float* x = 0; const int* ei = 0; const float* ev = 0;
    const float* W1 = 0; const float* W2 = 0;
    const float *a1s = 0, *a1d = 0, *b1 = 0, *a2s = 0, *a2d = 0, *b2 = 0;
    int n64 = 0, n8 = 0;
    for (int i = 0; i < n_in; i++) {
        int s = in_sizes[i];
        const void* p = d_in[i];
        if (!bytes_mode) {
            if      (s == NN * HID)   x  = (const float*)p;
            else if (s == 2 * EE)     ei = (const int*)p;
            else if (s == EE)         ev = (const float*)p;
            else if (s == HID * HID)  W1 = (const float*)p;
            else if (s == HID * OUTC) W2 = (const float*)p;
            else if (s == HID) { if (n64 == 0) a1s = (const float*)p; else if (n64 == 1) a1d = (const float*)p; else b1 = (const float*)p; n64++; }
            else if (s == OUTC) { if (n8 == 0) a2s = (const float*)p; else if (n8 == 1) a2d = (const float*)p; else b2 = (const float*)p; n8++; }
        } else {
            if (s == NN * HID * 4) { if (!x) x = (const float*)p; else if (!ei) ei = (const int*)p; }
            else if (s == 2 * EE * 4) ei = (const int*)p;
            else if (s == EE * 4)     ev = (const float*)p;
            else if (s == HID * HID * 4)  W1 = (const float*)p;
            else if (s == HID * OUTC * 4) W2 = (const float*)p;
            else if (s == HID * 4) { if (n64 == 0) a1s = (const float*)p; else if (n64 == 1) a1d = (const float*)p; else b1 = (const float*)p; n64++; }
            else if (s == OUTC * 4) { if (n8 == 0) a2s = (const float*)p; else if (n8 == 1) a2d = (const float*)p; else b2 = (const float*)p; n8++; }
        }
    }
    if (!x   && n_in > 0)  x   = (const float*)d_in[0];
    if (!ei  && n_in > 1)  ei  = (const int*)d_in[1];
    if (!ev  && n_in > 2)  ev  = (const float*)d_in[2];
    if (!W1  && n_in > 3)  W1  = (const float*)d_in[3];
    if (!a1s && n_in > 4)  a1s = (const float*)d_in[4];
    if (!a1d && n_in > 5)  a1d = (const float*)d_in[5];
    if (!b1  && n_in > 6)  b1  = (const float*)d_in[6];
    if (!W2  && n_in > 7)  W2  = (const float*)d_in[7];
    if (!a2s && n_in > 8)  a2s = (const float*)d_in[8];
    if (!a2d && n_in > 9)  a2d = (const float*)d_in[9];
    if (!b2  && n_in > 10) b2  = (const float*)d_in[10];
    if (!x || !ei || !ev || !W1 || !a1s || !a1d || !b1 || !W2 || !a2s || !a2d || !b2)
        return;
    float* out = (float*)d_out;

    // Fork k_gemm1 (independent of the bucket build) onto a side stream.
    cudaStream_t s2 = 0;
    cudaEvent_t evA = 0, evB = 0;
    bool forked =
        (cudaStreamCreateWithFlags(&s2, cudaStreamNonBlocking) == cudaSuccess) &&
        (cudaEventCreateWithFlags(&evA, cudaEventDisableTiming) == cudaSuccess) &&
        (cudaEventCreateWithFlags(&evB, cudaEventDisableTiming) == cudaSuccess);

    if (forked) {
        cudaEventRecord(evA, 0);
        cudaStreamWaitEvent(s2, evA, 0);
        k_gemm1<<<NN / 4, 256, 0, s2>>>(x, W1, a1s, a1d);
        cudaEventRecord(evB, s2);
    }

    // bucket build on the main stream
    k_init<<<(NN + 255) / 256, 256>>>(ei);
    k_scatter<<<(EE / 2 + 255) / 256, 256>>>(ei, ev);

    if (forked) {
        cudaStreamWaitEvent(0, evB, 0);   // join before agg1 consumes h1/es1/ed1
    } else {
        k_gemm1<<<NN / 4, 256>>>(x, W1, a1s, a1d);
    }

    k_agg1<<<(NN * 32 + 255) / 256, 256>>>(b1);
    k_gemm2<<<(NN + 31) / 32, 256>>>(W2, a2s, a2d);
    k_agg2<<<(NN * 32 + 255) / 256, 256>>>(b2, out);
}